// round 3
// baseline (speedup 1.0000x reference)
#include <cuda_runtime.h>
#include <cuda_fp16.h>
#include <cstddef>

#define BSZ 64
#define LSZ 1024
#define DSZ 256
#define NTOK (BSZ * LSZ)   // 65536 tokens

// ---------------- scratch (static __device__ — no allocations) ----------------
__device__ float   g_x [(size_t)NTOK * DSZ];        // 64 MB : inputs @ Wi + bi
__device__ float   g_xg[(size_t)NTOK * 3 * DSZ];    // 192 MB: [xx | xr' | xu'] per token
__device__ float   g_hf[(size_t)NTOK * DSZ];        // 64 MB : forward hidden states
__device__ float   g_hb[(size_t)NTOK * DSZ];        // 64 MB : backward hidden states
__device__ float   g_wg[DSZ * 3 * DSZ];             // packed [Wx | Ux | Rx]  (K x 768)
__device__ float   g_bg[3 * DSZ];                   // packed biases (Wr_b/Wu_b folded)
__device__ __half2 g_wp[DSZ * DSZ];                 // (Wr[k][j], Wu[k][j]) as half2

// ---------------- prep: pack gate weights / biases / fp16 recurrent weights ----
__global__ void prep_kernel(const float* __restrict__ Wx, const float* __restrict__ Wxb,
                            const float* __restrict__ Ux, const float* __restrict__ Uxb,
                            const float* __restrict__ Rx, const float* __restrict__ Rxb,
                            const float* __restrict__ Wr, const float* __restrict__ Wrb,
                            const float* __restrict__ Wu, const float* __restrict__ Wub) {
    int i = blockIdx.x * blockDim.x + threadIdx.x;

    if (i < DSZ * 3 * DSZ) {                    // g_wg[k*768 + n]
        int k = i / (3 * DSZ);
        int n = i % (3 * DSZ);
        float v;
        if (n < DSZ)            v = Wx[k * DSZ + n];
        else if (n < 2 * DSZ)   v = Ux[k * DSZ + (n - DSZ)];
        else                    v = Rx[k * DSZ + (n - 2 * DSZ)];
        g_wg[i] = v;
    }
    if (i < 3 * DSZ) {
        float v;
        if (i < DSZ)            v = Wxb[i];                       // xx bias
        else if (i < 2 * DSZ)   v = Uxb[i - DSZ] + Wrb[i - DSZ];  // xr bias + Wr bias
        else                    v = Rxb[i - 2 * DSZ] + Wub[i - 2 * DSZ];
        g_bg[i] = v;
    }
    if (i < DSZ * DSZ) {                        // g_wp[k*256 + j]
        int k = i / DSZ;
        int j = i % DSZ;
        g_wp[i] = __floats2half2_rn(Wr[k * DSZ + j], Wu[k * DSZ + j]);
    }
}

// ---------------- fp32 SIMT GEMM: C[M,N] = (A (+A2)) @ W[K=256,N] + bias -------
// 128x128 tile, 8x8 per thread, BK=8, 256 threads.
__global__ __launch_bounds__(256) void gemm_kernel(
        const float* __restrict__ A, const float* __restrict__ A2,
        const float* __restrict__ W, const float* __restrict__ bias,
        float* __restrict__ C, int Ncols) {
    __shared__ float As[8][128];
    __shared__ float Bs[8][128];

    const int bm = blockIdx.y * 128;
    const int bn = blockIdx.x * 128;
    const int tid = threadIdx.x;
    const int tx = tid & 15;        // 0..15 -> 8 cols each
    const int ty = tid >> 4;        // 0..15 -> 8 rows each

    // A loader: thread loads 4 floats; row = tid/2, kk-offset = (tid&1)*4
    const int arow = tid >> 1;
    const int acol = (tid & 1) * 4;
    const float* Aptr  = A  + (size_t)(bm + arow) * 256 + acol;
    const float* A2ptr = A2 ? (A2 + (size_t)(bm + arow) * 256 + acol) : nullptr;

    // B loader: row = tid/32 (0..7), col = (tid&31)*4
    const int brow = tid >> 5;
    const int bcol = (tid & 31) * 4;
    const float* Bptr = W + (size_t)brow * Ncols + bn + bcol;

    float acc[8][8];
#pragma unroll
    for (int i = 0; i < 8; i++)
#pragma unroll
        for (int j = 0; j < 8; j++) acc[i][j] = 0.f;

    for (int k0 = 0; k0 < 256; k0 += 8) {
        float4 av = *(const float4*)(Aptr + k0);
        if (A2ptr) {
            float4 a2 = *(const float4*)(A2ptr + k0);
            av.x += a2.x; av.y += a2.y; av.z += a2.z; av.w += a2.w;
        }
        float4 bv = *(const float4*)(Bptr + (size_t)k0 * Ncols);

        __syncthreads();   // previous tile fully consumed
        As[acol + 0][arow] = av.x;
        As[acol + 1][arow] = av.y;
        As[acol + 2][arow] = av.z;
        As[acol + 3][arow] = av.w;
        *(float4*)&Bs[brow][bcol] = bv;
        __syncthreads();

#pragma unroll
        for (int kk = 0; kk < 8; kk++) {
            float a[8], b[8];
            *(float4*)(a)     = *(const float4*)&As[kk][ty * 8];
            *(float4*)(a + 4) = *(const float4*)&As[kk][ty * 8 + 4];
            *(float4*)(b)     = *(const float4*)&Bs[kk][tx * 8];
            *(float4*)(b + 4) = *(const float4*)&Bs[kk][tx * 8 + 4];
#pragma unroll
            for (int i = 0; i < 8; i++)
#pragma unroll
                for (int j = 0; j < 8; j++)
                    acc[i][j] += a[i] * b[j];
        }
    }

#pragma unroll
    for (int j = 0; j < 8; j++) {
        float bv = bias[bn + tx * 8 + j];
#pragma unroll
        for (int i = 0; i < 8; i++) {
            C[(size_t)(bm + ty * 8 + i) * Ncols + bn + tx * 8 + j] = acc[i][j] + bv;
        }
    }
}

// ---------------- persistent GRU recurrence: 1 CTA per (batch, direction) -----
__global__ __launch_bounds__(256, 1) void gru_rec_kernel() {
    const int c   = blockIdx.x;
    const int b   = c >> 1;
    const int dir = c & 1;
    const int j   = threadIdx.x;

    __shared__ float hs[DSZ];
    hs[j] = 0.f;
    float hj = 0.f;
    float* __restrict__ hout = dir ? g_hb : g_hf;
    __syncthreads();

    for (int s = 0; s < LSZ; s++) {
        const int t = dir ? (LSZ - 1 - s) : s;
        const float* __restrict__ xrow = g_xg + ((size_t)b * LSZ + t) * (3 * DSZ);
        float ax = xrow[j];
        float ar = xrow[DSZ + j];
        float au = xrow[2 * DSZ + j];

        // ar += sum_k h[k] * Wr[k][j];  au += sum_k h[k] * Wu[k][j]
#pragma unroll 8
        for (int k = 0; k < DSZ; k += 4) {
            float4 h4 = *(const float4*)(hs + k);
            __half2 w0 = g_wp[(k + 0) * DSZ + j];
            __half2 w1 = g_wp[(k + 1) * DSZ + j];
            __half2 w2 = g_wp[(k + 2) * DSZ + j];
            __half2 w3 = g_wp[(k + 3) * DSZ + j];
            float2 f0 = __half22float2(w0); ar = fmaf(h4.x, f0.x, ar); au = fmaf(h4.x, f0.y, au);
            float2 f1 = __half22float2(w1); ar = fmaf(h4.y, f1.x, ar); au = fmaf(h4.y, f1.y, au);
            float2 f2 = __half22float2(w2); ar = fmaf(h4.z, f2.x, ar); au = fmaf(h4.z, f2.y, au);
            float2 f3 = __half22float2(w3); ar = fmaf(h4.w, f3.x, ar); au = fmaf(h4.w, f3.y, au);
        }

        float r = __fdividef(1.f, 1.f + __expf(-ar));
        float u = __fdividef(1.f, 1.f + __expf(-au));
        float xc = fmaf(r, hj, ax);
        float e  = __expf(-2.f * fabsf(xc));
        float th = __fdividef(1.f - e, 1.f + e);
        float cand = copysignf(th, xc);
        float hn = u * hj + (1.f - u) * cand;

        hout[((size_t)b * LSZ + t) * DSZ + j] = hn;

        __syncthreads();      // all dot-product reads of hs done
        hs[j] = hn;
        hj = hn;
        __syncthreads();      // publish new h
    }
}

// ---------------- launch ------------------------------------------------------
extern "C" void kernel_launch(void* const* d_in, const int* in_sizes, int n_in,
                              void* d_out, int out_size) {
    const float* inp  = (const float*)d_in[0];
    const float* Wi_w = (const float*)d_in[1];
    const float* Wi_b = (const float*)d_in[2];
    const float* Wx_w = (const float*)d_in[3];
    const float* Wx_b = (const float*)d_in[4];
    const float* Ux_w = (const float*)d_in[5];
    const float* Ux_b = (const float*)d_in[6];
    const float* Rx_w = (const float*)d_in[7];
    const float* Rx_b = (const float*)d_in[8];
    const float* Wr_w = (const float*)d_in[9];
    const float* Wr_b = (const float*)d_in[10];
    const float* Wu_w = (const float*)d_in[11];
    const float* Wu_b = (const float*)d_in[12];
    const float* Wo_w = (const float*)d_in[13];
    const float* Wo_b = (const float*)d_in[14];

    void *px, *pxg, *phf, *phb, *pwg, *pbg;
    cudaGetSymbolAddress(&px,  g_x);
    cudaGetSymbolAddress(&pxg, g_xg);
    cudaGetSymbolAddress(&phf, g_hf);
    cudaGetSymbolAddress(&phb, g_hb);
    cudaGetSymbolAddress(&pwg, g_wg);
    cudaGetSymbolAddress(&pbg, g_bg);

    // pack weights (covers max range 256*768 = 196608 elements)
    prep_kernel<<<768, 256>>>(Wx_w, Wx_b, Ux_w, Ux_b, Rx_w, Rx_b,
                              Wr_w, Wr_b, Wu_w, Wu_b);

    // x = inputs @ Wi + bi            [65536,256] x [256,256]
    gemm_kernel<<<dim3(2, 512), 256>>>(inp, nullptr, Wi_w, Wi_b, (float*)px, 256);

    // xg = x @ [Wx|Ux|Rx] + biases    [65536,256] x [256,768]
    gemm_kernel<<<dim3(6, 512), 256>>>((const float*)px, nullptr,
                                       (const float*)pwg, (const float*)pbg,
                                       (float*)pxg, 768);

    // bidirectional recurrence: 128 persistent CTAs
    gru_rec_kernel<<<128, 256>>>();

    // out = (hf + hb) @ Wo + bo       [65536,256] x [256,256]
    gemm_kernel<<<dim3(2, 512), 256>>>((const float*)phf, (const float*)phb,
                                       Wo_w, Wo_b, (float*)d_out, 256);
}

// round 4
// speedup vs baseline: 1.6904x; 1.6904x over previous
#include <cuda_runtime.h>
#include <cuda_fp16.h>
#include <cstddef>
#include <cstdint>

#define BSZ 64
#define LSZ 1024
#define DSZ 256
#define NTOK (BSZ * LSZ)   // 65536 tokens

// ---------------- scratch (static __device__ — no allocations) ----------------
__device__ __half  g_xh[(size_t)NTOK * DSZ];        // 32 MB : x = inputs @ Wi + bi  (fp16)
__device__ float   g_xg[(size_t)NTOK * 3 * DSZ];    // 192 MB: [xx | xr' | xu'] per token (fp32)
__device__ __half  g_hf[(size_t)NTOK * DSZ];        // 32 MB : forward hidden states (fp16)
__device__ __half  g_hb[(size_t)NTOK * DSZ];        // 32 MB : backward hidden states (fp16)
__device__ __half  g_wi_h[DSZ * DSZ];               // Wi fp16
__device__ __half  g_wo_h[DSZ * DSZ];               // Wo fp16
__device__ __half  g_wg_h[DSZ * 3 * DSZ];           // packed [Wx | Ux | Rx] fp16 (K x 768)
__device__ float   g_bg[3 * DSZ];                   // packed biases (Wr_b/Wu_b folded)
__device__ __half2 g_wp2[DSZ * DSZ];                // recurrent weights, uint4-packed layout

// ---------------- prep: pack weights / biases ---------------------------------
__global__ void prep_kernel(const float* __restrict__ Wi,
                            const float* __restrict__ Wx, const float* __restrict__ Wxb,
                            const float* __restrict__ Ux, const float* __restrict__ Uxb,
                            const float* __restrict__ Rx, const float* __restrict__ Rxb,
                            const float* __restrict__ Wr, const float* __restrict__ Wrb,
                            const float* __restrict__ Wu, const float* __restrict__ Wub,
                            const float* __restrict__ Wo) {
    int i = blockIdx.x * blockDim.x + threadIdx.x;

    if (i < DSZ * DSZ) {
        g_wi_h[i] = __float2half_rn(Wi[i]);
        g_wo_h[i] = __float2half_rn(Wo[i]);
        // packed recurrent layout: uint4 element (k>>2)*256 + j holds half2 pairs
        // (Wr[k+c][j], Wu[k+c][j]) for c = 0..3
        int k = i >> 8, j = i & 255;
        g_wp2[(size_t)(k >> 2) * 1024 + j * 4 + (k & 3)] =
            __floats2half2_rn(Wr[i], Wu[i]);
    }
    if (i < DSZ * 3 * DSZ) {                    // g_wg_h[k*768 + n]
        int k = i / (3 * DSZ);
        int n = i % (3 * DSZ);
        float v;
        if (n < DSZ)            v = Wx[k * DSZ + n];
        else if (n < 2 * DSZ)   v = Ux[k * DSZ + (n - DSZ)];
        else                    v = Rx[k * DSZ + (n - 2 * DSZ)];
        g_wg_h[i] = __float2half_rn(v);
    }
    if (i < 3 * DSZ) {
        float v;
        if (i < DSZ)            v = Wxb[i];                       // xx bias
        else if (i < 2 * DSZ)   v = Uxb[i - DSZ] + Wrb[i - DSZ];  // xr bias + Wr bias
        else                    v = Rxb[i - 2 * DSZ] + Wub[i - 2 * DSZ];
        g_bg[i] = v;
    }
}

// ---------------- tensor-core GEMM: C[M,N] = A[M,256] @ B[256,N] + bias --------
// CTA tile 128x128, K=256 one-shot in smem, 8 warps, warp tile 32x64.
// AMODE: 0 = A fp32 global (convert), 1 = A fp16 global, 2 = A = fp16(A)+fp16(A2)
// OUTH : 0 = fp32 output, 1 = fp16 output
#define A_LD 264   // halfs per A smem row (128 rows x 256 k, pad 8)
#define B_LD 136   // halfs per B smem row (256 rows x 128 n, pad 8)
#define SMEM_GEMM_BYTES ((128 * A_LD + 256 * B_LD) * 2)

__device__ __forceinline__ void ldmatrix_x4(uint32_t* r, const __half* p) {
    uint32_t addr = (uint32_t)__cvta_generic_to_shared(p);
    asm volatile("ldmatrix.sync.aligned.m8n8.x4.shared.b16 {%0,%1,%2,%3}, [%4];"
                 : "=r"(r[0]), "=r"(r[1]), "=r"(r[2]), "=r"(r[3]) : "r"(addr));
}
__device__ __forceinline__ void ldmatrix_x2t(uint32_t* r, const __half* p) {
    uint32_t addr = (uint32_t)__cvta_generic_to_shared(p);
    asm volatile("ldmatrix.sync.aligned.m8n8.x2.trans.shared.b16 {%0,%1}, [%2];"
                 : "=r"(r[0]), "=r"(r[1]) : "r"(addr));
}
__device__ __forceinline__ void mma16816(float* c, const uint32_t* a, const uint32_t* b) {
    asm volatile("mma.sync.aligned.m16n8k16.row.col.f32.f16.f16.f32 "
                 "{%0,%1,%2,%3}, {%4,%5,%6,%7}, {%8,%9}, {%0,%1,%2,%3};"
                 : "+f"(c[0]), "+f"(c[1]), "+f"(c[2]), "+f"(c[3])
                 : "r"(a[0]), "r"(a[1]), "r"(a[2]), "r"(a[3]), "r"(b[0]), "r"(b[1]));
}

template<int AMODE, int OUTH>
__global__ __launch_bounds__(256) void gemm_tc(
        const void* __restrict__ Aa, const void* __restrict__ Ab,
        const __half* __restrict__ Bg, const float* __restrict__ bias,
        void* __restrict__ Cg, int N) {
    extern __shared__ __half sm[];
    __half* As = sm;                     // [128][A_LD]
    __half* Bs = sm + 128 * A_LD;       // [256][B_LD]

    const int tid  = threadIdx.x;
    const int bm   = blockIdx.y * 128;
    const int bn   = blockIdx.x * 128;

    // ---- load A tile (128 x 256 halfs = 4096 uint4) ----
#pragma unroll
    for (int it = 0; it < 16; it++) {
        int idx = it * 256 + tid;
        int row = idx >> 5;             // 32 uint4 per row
        int cu  = idx & 31;
        uint4 v;
        if (AMODE == 0) {
            const float4* Af = (const float4*)Aa;
            size_t base = (size_t)(bm + row) * 64 + cu * 2;
            float4 x0 = Af[base], x1 = Af[base + 1];
            __half2 hh[4] = { __floats2half2_rn(x0.x, x0.y), __floats2half2_rn(x0.z, x0.w),
                              __floats2half2_rn(x1.x, x1.y), __floats2half2_rn(x1.z, x1.w) };
            v = *(uint4*)hh;
        } else if (AMODE == 1) {
            v = ((const uint4*)Aa)[(size_t)(bm + row) * 32 + cu];
        } else {
            uint4 p = ((const uint4*)Aa)[(size_t)(bm + row) * 32 + cu];
            uint4 q = ((const uint4*)Ab)[(size_t)(bm + row) * 32 + cu];
            __half2* pp = (__half2*)&p; const __half2* qq = (const __half2*)&q;
            pp[0] = __hadd2(pp[0], qq[0]); pp[1] = __hadd2(pp[1], qq[1]);
            pp[2] = __hadd2(pp[2], qq[2]); pp[3] = __hadd2(pp[3], qq[3]);
            v = p;
        }
        *(uint4*)(As + row * A_LD + cu * 8) = v;
    }
    // ---- load B tile (256 x 128 halfs = 4096 uint4) ----
    const int nq = N >> 3;
#pragma unroll
    for (int it = 0; it < 16; it++) {
        int idx = it * 256 + tid;
        int row = idx >> 4;             // 16 uint4 per row
        int cu  = idx & 15;
        uint4 v = ((const uint4*)Bg)[(size_t)row * nq + (bn >> 3) + cu];
        *(uint4*)(Bs + row * B_LD + cu * 8) = v;
    }
    __syncthreads();

    const int wid  = tid >> 5;
    const int lane = tid & 31;
    const int wm   = (wid & 3) * 32;    // warp m-offset
    const int wn   = (wid >> 2) * 64;   // warp n-offset

    float acc[2][8][4];
#pragma unroll
    for (int mt = 0; mt < 2; mt++)
#pragma unroll
        for (int nt = 0; nt < 8; nt++)
#pragma unroll
            for (int i = 0; i < 4; i++) acc[mt][nt][i] = 0.f;

    const int al_r = lane & 15;
    const int al_c = (lane >> 4) << 3;
#pragma unroll
    for (int ks = 0; ks < 16; ks++) {
        const int k0 = ks * 16;
        uint32_t a[2][4], b[8][2];
#pragma unroll
        for (int mt = 0; mt < 2; mt++)
            ldmatrix_x4(a[mt], As + (wm + mt * 16 + al_r) * A_LD + k0 + al_c);
#pragma unroll
        for (int nt = 0; nt < 8; nt++)
            ldmatrix_x2t(b[nt], Bs + (k0 + al_r) * B_LD + wn + nt * 8);
#pragma unroll
        for (int mt = 0; mt < 2; mt++)
#pragma unroll
            for (int nt = 0; nt < 8; nt++)
                mma16816(acc[mt][nt], a[mt], b[nt]);
    }

    // ---- epilogue ----
#pragma unroll
    for (int mt = 0; mt < 2; mt++) {
#pragma unroll
        for (int nt = 0; nt < 8; nt++) {
            int row = bm + wm + mt * 16 + (lane >> 2);
            int col = bn + wn + nt * 8 + (lane & 3) * 2;
            float b0 = bias[col], b1 = bias[col + 1];
            if (OUTH) {
                __half* C = (__half*)Cg;
                *(__half2*)(C + (size_t)row * N + col) =
                    __floats2half2_rn(acc[mt][nt][0] + b0, acc[mt][nt][1] + b1);
                *(__half2*)(C + (size_t)(row + 8) * N + col) =
                    __floats2half2_rn(acc[mt][nt][2] + b0, acc[mt][nt][3] + b1);
            } else {
                float* C = (float*)Cg;
                *(float2*)(C + (size_t)row * N + col) =
                    make_float2(acc[mt][nt][0] + b0, acc[mt][nt][1] + b1);
                *(float2*)(C + (size_t)(row + 8) * N + col) =
                    make_float2(acc[mt][nt][2] + b0, acc[mt][nt][3] + b1);
            }
        }
    }
}

// ---------------- persistent GRU recurrence: 1 CTA per (batch, direction) -----
// 512 threads: 2 threads per output j, each sums 128 of the 256 k-terms.
__global__ __launch_bounds__(512, 1) void gru_rec_kernel() {
    const int cta  = blockIdx.x;
    const int b    = cta >> 1;
    const int dir  = cta & 1;
    const int tid  = threadIdx.x;
    const int j    = tid & 255;
    const int half = tid >> 8;

    __shared__ float hs[DSZ];
    __shared__ float pr[512];
    __shared__ float pu[512];

    __half* __restrict__ hout = dir ? g_hb : g_hf;
    if (tid < 256) hs[tid] = 0.f;
    float hj = 0.f;
    __syncthreads();

    const size_t browbase = (size_t)b * LSZ;
    // uint4 element (k>>2)*256 + j; this thread's k range starts at half*128
    const uint4*  wp = (const uint4*)g_wp2 + half * 32 * 256 + j;
    const float4* hv = (const float4*)hs + half * 32;

    for (int s = 0; s < LSZ; s++) {
        const int t = dir ? (LSZ - 1 - s) : s;
        const float* __restrict__ xrow = g_xg + (browbase + t) * (3 * DSZ);
        float ax = 0.f, axr = 0.f, axu = 0.f;
        if (half == 0) {                // streaming loads, evict-first (protect weight L1)
            ax  = __ldcs(xrow + j);
            axr = __ldcs(xrow + 256 + j);
            axu = __ldcs(xrow + 512 + j);
        }

        float ar = 0.f, au = 0.f;
#pragma unroll 8
        for (int i = 0; i < 32; i++) {
            uint4  w  = wp[(size_t)i * 256];    // LDG.128: 4 k of (Wr,Wu) half2
            float4 h4 = hv[i];                  // LDS.128 broadcast
            const __half2* wh = (const __half2*)&w;
            float2 f0 = __half22float2(wh[0]); ar = fmaf(h4.x, f0.x, ar); au = fmaf(h4.x, f0.y, au);
            float2 f1 = __half22float2(wh[1]); ar = fmaf(h4.y, f1.x, ar); au = fmaf(h4.y, f1.y, au);
            float2 f2 = __half22float2(wh[2]); ar = fmaf(h4.z, f2.x, ar); au = fmaf(h4.z, f2.y, au);
            float2 f3 = __half22float2(wh[3]); ar = fmaf(h4.w, f3.x, ar); au = fmaf(h4.w, f3.y, au);
        }
        pr[tid] = ar;
        pu[tid] = au;
        __syncthreads();

        if (tid < 256) {
            float gr = pr[tid] + pr[tid + 256] + axr;
            float gu = pu[tid] + pu[tid + 256] + axu;
            float r  = __fdividef(1.f, 1.f + __expf(-gr));
            float u  = __fdividef(1.f, 1.f + __expf(-gu));
            float xc = fmaf(r, hj, ax);
            float e  = __expf(-2.f * fabsf(xc));
            float th = __fdividef(1.f - e, 1.f + e);
            float cand = copysignf(th, xc);
            float hn = u * hj + (1.f - u) * cand;

            hout[(browbase + t) * DSZ + tid] = __float2half_rn(hn);
            hs[tid] = hn;
            hj = hn;
        }
        __syncthreads();
    }
}

// ---------------- launch ------------------------------------------------------
extern "C" void kernel_launch(void* const* d_in, const int* in_sizes, int n_in,
                              void* d_out, int out_size) {
    const float* inp  = (const float*)d_in[0];
    const float* Wi_w = (const float*)d_in[1];
    const float* Wi_b = (const float*)d_in[2];
    const float* Wx_w = (const float*)d_in[3];
    const float* Wx_b = (const float*)d_in[4];
    const float* Ux_w = (const float*)d_in[5];
    const float* Ux_b = (const float*)d_in[6];
    const float* Rx_w = (const float*)d_in[7];
    const float* Rx_b = (const float*)d_in[8];
    const float* Wr_w = (const float*)d_in[9];
    const float* Wr_b = (const float*)d_in[10];
    const float* Wu_w = (const float*)d_in[11];
    const float* Wu_b = (const float*)d_in[12];
    const float* Wo_w = (const float*)d_in[13];
    const float* Wo_b = (const float*)d_in[14];

    void *pxh, *pxg, *phf, *phb, *pwi, *pwg, *pwo, *pbg;
    cudaGetSymbolAddress(&pxh, g_xh);
    cudaGetSymbolAddress(&pxg, g_xg);
    cudaGetSymbolAddress(&phf, g_hf);
    cudaGetSymbolAddress(&phb, g_hb);
    cudaGetSymbolAddress(&pwi, g_wi_h);
    cudaGetSymbolAddress(&pwg, g_wg_h);
    cudaGetSymbolAddress(&pwo, g_wo_h);
    cudaGetSymbolAddress(&pbg, g_bg);

    cudaFuncSetAttribute(gemm_tc<0, 1>, cudaFuncAttributeMaxDynamicSharedMemorySize, SMEM_GEMM_BYTES);
    cudaFuncSetAttribute(gemm_tc<1, 0>, cudaFuncAttributeMaxDynamicSharedMemorySize, SMEM_GEMM_BYTES);
    cudaFuncSetAttribute(gemm_tc<2, 0>, cudaFuncAttributeMaxDynamicSharedMemorySize, SMEM_GEMM_BYTES);

    // pack weights (196608 threads covers everything)
    prep_kernel<<<768, 256>>>(Wi_w, Wx_w, Wx_b, Ux_w, Ux_b, Rx_w, Rx_b,
                              Wr_w, Wr_b, Wu_w, Wu_b, Wo_w);

    // x = fp16(inputs @ Wi + bi)          [65536,256] x [256,256]
    gemm_tc<0, 1><<<dim3(2, 512), 256, SMEM_GEMM_BYTES>>>(
        inp, nullptr, (const __half*)pwi, Wi_b, pxh, 256);

    // xg = x @ [Wx|Ux|Rx] + biases        [65536,256] x [256,768] -> fp32
    gemm_tc<1, 0><<<dim3(6, 512), 256, SMEM_GEMM_BYTES>>>(
        pxh, nullptr, (const __half*)pwg, (const float*)pbg, pxg, 768);

    // bidirectional recurrence: 128 persistent CTAs x 512 threads
    gru_rec_kernel<<<128, 512>>>();

    // out = (hf + hb) @ Wo + bo           [65536,256] x [256,256] -> fp32
    gemm_tc<2, 0><<<dim3(2, 512), 256, SMEM_GEMM_BYTES>>>(
        phf, phb, (const __half*)pwo, Wo_b, d_out, 256);
}

// round 6
// speedup vs baseline: 3.4801x; 2.0587x over previous
#include <cuda_runtime.h>
#include <cuda_fp16.h>
#include <cstddef>
#include <cstdint>

#define BSZ 64
#define LSZ 1024
#define DSZ 256
#define NTOK (BSZ * LSZ)   // 65536 tokens

// ---------------- scratch (static __device__ — no allocations) ----------------
__device__ __half  g_xh[(size_t)NTOK * DSZ];        // 32 MB : x = inputs @ Wi + bi  (fp16)
__device__ float   g_xg[(size_t)NTOK * 3 * DSZ];    // 192 MB: [xx | xr' | xu'] per token (fp32)
__device__ __half  g_hf[(size_t)NTOK * DSZ];        // 32 MB : forward hidden states (fp16)
__device__ __half  g_hb[(size_t)NTOK * DSZ];        // 32 MB : backward hidden states (fp16)
__device__ __half  g_wi_h[DSZ * DSZ];               // Wi fp16
__device__ __half  g_wo_h[DSZ * DSZ];               // Wo fp16
__device__ __half  g_wg_h[DSZ * 3 * DSZ];           // packed [Wx | Ux | Rx] fp16 (K x 768)
__device__ float   g_bg[3 * DSZ];                   // packed biases (Wr_b/Wu_b folded)
// recurrent weights for tc kernel: [q][k=256][n'=128] ; n'<64 -> Wr[:,q*64+n'], else Wu
__device__ __half  g_wrec[4 * 256 * 128];

// ---------------- prep: pack weights / biases ---------------------------------
__global__ void prep_kernel(const float* __restrict__ Wi,
                            const float* __restrict__ Wx, const float* __restrict__ Wxb,
                            const float* __restrict__ Ux, const float* __restrict__ Uxb,
                            const float* __restrict__ Rx, const float* __restrict__ Rxb,
                            const float* __restrict__ Wr, const float* __restrict__ Wrb,
                            const float* __restrict__ Wu, const float* __restrict__ Wub,
                            const float* __restrict__ Wo) {
    int i = blockIdx.x * blockDim.x + threadIdx.x;

    if (i < DSZ * DSZ) {
        g_wi_h[i] = __float2half_rn(Wi[i]);
        g_wo_h[i] = __float2half_rn(Wo[i]);
    }
    if (i < 4 * 256 * 128) {                    // recurrent weight slices
        int q = i >> 15;
        int k = (i >> 7) & 255;
        int n = i & 127;
        int col = q * 64 + (n < 64 ? n : n - 64);
        float v = (n < 64) ? Wr[k * DSZ + col] : Wu[k * DSZ + col];
        g_wrec[i] = __float2half_rn(v);
    }
    if (i < DSZ * 3 * DSZ) {                    // g_wg_h[k*768 + n]
        int k = i / (3 * DSZ);
        int n = i % (3 * DSZ);
        float v;
        if (n < DSZ)            v = Wx[k * DSZ + n];
        else if (n < 2 * DSZ)   v = Ux[k * DSZ + (n - DSZ)];
        else                    v = Rx[k * DSZ + (n - 2 * DSZ)];
        g_wg_h[i] = __float2half_rn(v);
    }
    if (i < 3 * DSZ) {
        float v;
        if (i < DSZ)            v = Wxb[i];                       // xx bias
        else if (i < 2 * DSZ)   v = Uxb[i - DSZ] + Wrb[i - DSZ];  // xr bias + Wr bias
        else                    v = Rxb[i - 2 * DSZ] + Wub[i - 2 * DSZ];
        g_bg[i] = v;
    }
}

// ---------------- mma / ldmatrix helpers --------------------------------------
__device__ __forceinline__ void ldmatrix_x4(uint32_t* r, const __half* p) {
    uint32_t addr = (uint32_t)__cvta_generic_to_shared(p);
    asm volatile("ldmatrix.sync.aligned.m8n8.x4.shared.b16 {%0,%1,%2,%3}, [%4];"
                 : "=r"(r[0]), "=r"(r[1]), "=r"(r[2]), "=r"(r[3]) : "r"(addr));
}
__device__ __forceinline__ void ldmatrix_x2t(uint32_t* r, const __half* p) {
    uint32_t addr = (uint32_t)__cvta_generic_to_shared(p);
    asm volatile("ldmatrix.sync.aligned.m8n8.x2.trans.shared.b16 {%0,%1}, [%2];"
                 : "=r"(r[0]), "=r"(r[1]) : "r"(addr));
}
__device__ __forceinline__ void mma16816(float* c, const uint32_t* a, const uint32_t* b) {
    asm volatile("mma.sync.aligned.m16n8k16.row.col.f32.f16.f16.f32 "
                 "{%0,%1,%2,%3}, {%4,%5,%6,%7}, {%8,%9}, {%0,%1,%2,%3};"
                 : "+f"(c[0]), "+f"(c[1]), "+f"(c[2]), "+f"(c[3])
                 : "r"(a[0]), "r"(a[1]), "r"(a[2]), "r"(a[3]), "r"(b[0]), "r"(b[1]));
}

// ---------------- mbarrier / cluster helpers ----------------------------------
__device__ __forceinline__ void bar_init(uint32_t bar, uint32_t cnt) {
    asm volatile("mbarrier.init.shared.b64 [%0], %1;" :: "r"(bar), "r"(cnt) : "memory");
}
__device__ __forceinline__ void bar_expect_tx(uint32_t bar, uint32_t bytes) {
    asm volatile("mbarrier.arrive.expect_tx.shared.b64 _, [%0], %1;"
                 :: "r"(bar), "r"(bytes) : "memory");
}
__device__ __forceinline__ void bar_wait(uint32_t bar, uint32_t phase) {
    asm volatile(
        "{\n\t.reg .pred P;\n\t"
        "WL_%=:\n\t"
        "mbarrier.try_wait.parity.acquire.cta.shared::cta.b64 P, [%0], %1, 0x989680;\n\t"
        "@P bra WD_%=;\n\t"
        "bra WL_%=;\n\t"
        "WD_%=:\n\t}"
        :: "r"(bar), "r"(phase) : "memory");
}
__device__ __forceinline__ uint32_t mapa_u32(uint32_t laddr, uint32_t rank) {
    uint32_t r;
    asm volatile("mapa.shared::cluster.u32 %0, %1, %2;" : "=r"(r) : "r"(laddr), "r"(rank));
    return r;
}
__device__ __forceinline__ void st_async_b32(uint32_t raddr, uint32_t val, uint32_t rbar) {
    asm volatile("st.async.shared::cluster.mbarrier::complete_tx::bytes.b32 [%0], %1, [%2];"
                 :: "r"(raddr), "r"(val), "r"(rbar) : "memory");
}

// ---------------- tensor-core GEMM: C[M,N] = A[M,256] @ B[256,N] + bias --------
// (unchanged from R4 — validated)
#define A_LD 264
#define B_LD 136
#define SMEM_GEMM_BYTES ((128 * A_LD + 256 * B_LD) * 2)

template<int AMODE, int OUTH>
__global__ __launch_bounds__(256) void gemm_tc(
        const void* __restrict__ Aa, const void* __restrict__ Ab,
        const __half* __restrict__ Bg, const float* __restrict__ bias,
        void* __restrict__ Cg, int N) {
    extern __shared__ __half sm[];
    __half* As = sm;                     // [128][A_LD]
    __half* Bs = sm + 128 * A_LD;        // [256][B_LD]

    const int tid  = threadIdx.x;
    const int bm   = blockIdx.y * 128;
    const int bn   = blockIdx.x * 128;

#pragma unroll
    for (int it = 0; it < 16; it++) {
        int idx = it * 256 + tid;
        int row = idx >> 5;
        int cu  = idx & 31;
        uint4 v;
        if (AMODE == 0) {
            const float4* Af = (const float4*)Aa;
            size_t base = (size_t)(bm + row) * 64 + cu * 2;
            float4 x0 = Af[base], x1 = Af[base + 1];
            __half2 hh[4] = { __floats2half2_rn(x0.x, x0.y), __floats2half2_rn(x0.z, x0.w),
                              __floats2half2_rn(x1.x, x1.y), __floats2half2_rn(x1.z, x1.w) };
            v = *(uint4*)hh;
        } else if (AMODE == 1) {
            v = ((const uint4*)Aa)[(size_t)(bm + row) * 32 + cu];
        } else {
            uint4 p = ((const uint4*)Aa)[(size_t)(bm + row) * 32 + cu];
            uint4 q = ((const uint4*)Ab)[(size_t)(bm + row) * 32 + cu];
            __half2* pp = (__half2*)&p; const __half2* qq = (const __half2*)&q;
            pp[0] = __hadd2(pp[0], qq[0]); pp[1] = __hadd2(pp[1], qq[1]);
            pp[2] = __hadd2(pp[2], qq[2]); pp[3] = __hadd2(pp[3], qq[3]);
            v = p;
        }
        *(uint4*)(As + row * A_LD + cu * 8) = v;
    }
    const int nq = N >> 3;
#pragma unroll
    for (int it = 0; it < 16; it++) {
        int idx = it * 256 + tid;
        int row = idx >> 4;
        int cu  = idx & 15;
        uint4 v = ((const uint4*)Bg)[(size_t)row * nq + (bn >> 3) + cu];
        *(uint4*)(Bs + row * B_LD + cu * 8) = v;
    }
    __syncthreads();

    const int wid  = tid >> 5;
    const int lane = tid & 31;
    const int wm   = (wid & 3) * 32;
    const int wn   = (wid >> 2) * 64;

    float acc[2][8][4];
#pragma unroll
    for (int mt = 0; mt < 2; mt++)
#pragma unroll
        for (int nt = 0; nt < 8; nt++)
#pragma unroll
            for (int i = 0; i < 4; i++) acc[mt][nt][i] = 0.f;

    const int al_r = lane & 15;
    const int al_c = (lane >> 4) << 3;
#pragma unroll
    for (int ks = 0; ks < 16; ks++) {
        const int k0 = ks * 16;
        uint32_t a[2][4], b[8][2];
#pragma unroll
        for (int mt = 0; mt < 2; mt++)
            ldmatrix_x4(a[mt], As + (wm + mt * 16 + al_r) * A_LD + k0 + al_c);
#pragma unroll
        for (int nt = 0; nt < 8; nt++)
            ldmatrix_x2t(b[nt], Bs + (k0 + al_r) * B_LD + wn + nt * 8);
#pragma unroll
        for (int mt = 0; mt < 2; mt++)
#pragma unroll
            for (int nt = 0; nt < 8; nt++)
                mma16816(acc[mt][nt], a[mt], b[nt]);
    }

#pragma unroll
    for (int mt = 0; mt < 2; mt++) {
#pragma unroll
        for (int nt = 0; nt < 8; nt++) {
            int row = bm + wm + mt * 16 + (lane >> 2);
            int col = bn + wn + nt * 8 + (lane & 3) * 2;
            float b0 = bias[col], b1 = bias[col + 1];
            if (OUTH) {
                __half* C = (__half*)Cg;
                *(__half2*)(C + (size_t)row * N + col) =
                    __floats2half2_rn(acc[mt][nt][0] + b0, acc[mt][nt][1] + b1);
                *(__half2*)(C + (size_t)(row + 8) * N + col) =
                    __floats2half2_rn(acc[mt][nt][2] + b0, acc[mt][nt][3] + b1);
            } else {
                float* C = (float*)Cg;
                *(float2*)(C + (size_t)row * N + col) =
                    make_float2(acc[mt][nt][0] + b0, acc[mt][nt][1] + b1);
                *(float2*)(C + (size_t)(row + 8) * N + col) =
                    make_float2(acc[mt][nt][2] + b0, acc[mt][nt][3] + b1);
            }
        }
    }
}

// ---------------- tensor-core GRU recurrence ----------------------------------
// 8 groups x 16 sequences; each group = cluster of 4 CTAs splitting the 128
// gate columns (64 j each, r-cols 0..63 / u-cols 64..127 of its slice).
// Weights live in registers as mma B-fragments. h exchanged via st.async + tx-mbarrier.
#define HS_PITCH 264                     // halfs per h-stage row
#define P_PITCH  132                     // floats per partial row
#define HS_BYTES (2 * 16 * HS_PITCH * 2) // 16896
#define P_OFF    HS_BYTES
#define P_BYTES  (4 * 16 * P_PITCH * 4)  // 33792
#define WST_OFF  0                       // weight stage overlaps runtime bufs
#define WST_PITCH 136
#define WST_BYTES (256 * WST_PITCH * 2)  // 69632
#define BAR_OFF  WST_BYTES
#define GRU_SMEM (WST_BYTES + 64)

__global__ __launch_bounds__(512, 1) __cluster_dims__(4, 1, 1)
void gru_rec_tc() {
    extern __shared__ char smc[];
    __half* wstage = (__half*)(smc + WST_OFF);
    __half* hstage = (__half*)smc;                 // [2][16][HS_PITCH]
    float*  Pbuf   = (float*)(smc + P_OFF);        // [4][16][P_PITCH]
    const uint32_t smb   = (uint32_t)__cvta_generic_to_shared(smc);
    const uint32_t barb  = smb + BAR_OFF;

    const int tid  = threadIdx.x;
    const int wid  = tid >> 5;
    const int lane = tid & 31;
    uint32_t rank;
    asm("mov.u32 %0, %%cluster_ctarank;" : "=r"(rank));
    const int q = (int)rank;
    const int g = blockIdx.x >> 2;

    // ---- stage this CTA's 64KB weight slice, then ldmatrix into registers ----
    {
        const uint4* src = (const uint4*)g_wrec + (size_t)q * 4096;
#pragma unroll
        for (int it = 0; it < 8; it++) {
            int idx = it * 512 + tid;
            int row = idx >> 4;
            int cu  = idx & 15;
            *(uint4*)(wstage + row * WST_PITCH + cu * 8) = src[idx];
        }
    }
    __syncthreads();

    const int kq = wid & 3;     // k-quarter: k in [kq*64, kq*64+64)
    const int nql = wid >> 2;   // n-quarter: n' in [nql*32, nql*32+32)
    uint32_t Breg[4][4][2];
#pragma unroll
    for (int kk = 0; kk < 4; kk++)
#pragma unroll
        for (int nt = 0; nt < 4; nt++)
            ldmatrix_x2t(Breg[kk][nt],
                         wstage + (kq * 64 + kk * 16 + (lane & 15)) * WST_PITCH
                                + nql * 32 + nt * 8);
    __syncthreads();   // weight stage dead; smem reused for hstage/Pbuf

    if (tid == 0) { bar_init(barb, 1); bar_init(barb + 8, 1); }
    asm volatile("barrier.cluster.arrive.aligned;" ::: "memory");
    asm volatile("barrier.cluster.wait.aligned;" ::: "memory");

    // ---- per-thread elementwise identity: one row (=warp), two adjacent j ----
    const int row = wid;                 // 0..15  (sequence within group)
    const int jl  = (lane) * 2;          // 0..62 local j pair
    const int jg  = q * 64 + jl;         // global j
    const int c   = g * 16 + row;
    const int b   = c >> 1;
    const int dir = c & 1;
    const size_t browb = (size_t)b * LSZ;
    __half* __restrict__ hout = dir ? g_hb : g_hf;

    float hvx = 0.f, hvy = 0.f;          // fp32 recurrent state (exact)

    // prefetch xg for s=0
    float2 xx_c, xr_c, xu_c;
    {
        int t0 = dir ? (LSZ - 1) : 0;
        const float* xgp = g_xg + (browb + t0) * (3 * DSZ);
        xx_c = *(const float2*)(xgp + jg);
        xr_c = *(const float2*)(xgp + 256 + jg);
        xu_c = *(const float2*)(xgp + 512 + jg);
    }

    const uint32_t hs_l0 = smb;                      // hstage base (shared addr)
    const int al_r = lane & 15;
    const int al_c = (lane >> 4) << 3;

    for (int s = 0; s < LSZ; s++) {
        const int bb = s & 1, nb = bb ^ 1;

        // prefetch next step's xg (hides DRAM latency behind the whole step)
        float2 xx_n, xr_n, xu_n;
        if (s < LSZ - 1) {
            int tn = dir ? (LSZ - 2 - s) : (s + 1);
            const float* xgp = g_xg + (browb + tn) * (3 * DSZ);
            xx_n = *(const float2*)(xgp + jg);
            xr_n = *(const float2*)(xgp + 256 + jg);
            xu_n = *(const float2*)(xgp + 512 + jg);
        }
        if (tid == 0 && s < LSZ - 1) bar_expect_tx(barb + nb * 8, 8192);

        float rpx = 0.f, rpy = 0.f, upx = 0.f, upy = 0.f;
        if (s > 0) {
            // wait for h(s) staged in buffer bb (tx from all 4 CTAs)
            int n = (s & 1) ? ((s - 1) >> 1) : ((s >> 1) - 1);
            bar_wait(barb + bb * 8, (uint32_t)(n & 1));

            // ---- mma: C[16 x 32slice] += h[16 x k-quarter] @ W ----
            float acc[4][4];
#pragma unroll
            for (int nt = 0; nt < 4; nt++)
#pragma unroll
                for (int i = 0; i < 4; i++) acc[nt][i] = 0.f;
            const __half* hcur = hstage + bb * 16 * HS_PITCH;
#pragma unroll
            for (int kk = 0; kk < 4; kk++) {
                uint32_t a[4];
                ldmatrix_x4(a, hcur + al_r * HS_PITCH + kq * 64 + kk * 16 + al_c);
#pragma unroll
                for (int nt = 0; nt < 4; nt++)
                    mma16816(acc[nt], a, Breg[kk][nt]);
            }
            // ---- STS partial sums: P[kq][row][col] ----
            {
                int r0 = lane >> 2, cp = (lane & 3) * 2;
#pragma unroll
                for (int nt = 0; nt < 4; nt++) {
                    int col = nql * 32 + nt * 8 + cp;
                    float* p = Pbuf + (kq * 16 + r0) * P_PITCH + col;
                    *(float2*)p = make_float2(acc[nt][0], acc[nt][1]);
                    *(float2*)(p + 8 * P_PITCH) = make_float2(acc[nt][2], acc[nt][3]);
                }
            }
            __syncthreads();
            // ---- reduce 4 k-partials for this thread's (row, jl, jl+1) ----
#pragma unroll
            for (int k2 = 0; k2 < 4; k2++) {
                const float* pp = Pbuf + (k2 * 16 + row) * P_PITCH;
                float2 a = *(const float2*)(pp + jl);
                float2 bq = *(const float2*)(pp + 64 + jl);
                rpx += a.x; rpy += a.y; upx += bq.x; upy += bq.y;
            }
        }

        // ---- elementwise gates (exp-based, same math as R4) ----
        float grx = rpx + xr_c.x, gry = rpy + xr_c.y;
        float gux = upx + xu_c.x, guy = upy + xu_c.y;
        float r0 = __fdividef(1.f, 1.f + __expf(-grx));
        float r1 = __fdividef(1.f, 1.f + __expf(-gry));
        float u0 = __fdividef(1.f, 1.f + __expf(-gux));
        float u1 = __fdividef(1.f, 1.f + __expf(-guy));
        float xc0 = fmaf(r0, hvx, xx_c.x);
        float xc1 = fmaf(r1, hvy, xx_c.y);
        float e0 = __expf(-2.f * fabsf(xc0));
        float e1 = __expf(-2.f * fabsf(xc1));
        float th0 = copysignf(__fdividef(1.f - e0, 1.f + e0), xc0);
        float th1 = copysignf(__fdividef(1.f - e1, 1.f + e1), xc1);
        float hn0 = u0 * hvx + (1.f - u0) * th0;
        float hn1 = u1 * hvy + (1.f - u1) * th1;
        hvx = hn0; hvy = hn1;

        // ---- write out + stage h(s+1) into all 4 cluster CTAs ----
        const int t = dir ? (LSZ - 1 - s) : s;
        __half2 hh = __floats2half2_rn(hn0, hn1);
        *(__half2*)(hout + (browb + t) * DSZ + jg) = hh;

        if (s < LSZ - 1) {
            uint32_t val = *(uint32_t*)&hh;
            uint32_t laddr = hs_l0 + ((nb * 16 + row) * HS_PITCH + jg) * 2;
            uint32_t lbar  = barb + nb * 8;
#pragma unroll
            for (int rr = 0; rr < 4; rr++) {
                uint32_t ra  = mapa_u32(laddr, (uint32_t)rr);
                uint32_t rb2 = mapa_u32(lbar,  (uint32_t)rr);
                st_async_b32(ra, val, rb2);
            }
        }
        __syncthreads();    // P WAR protection for next step's STS
        xx_c = xx_n; xr_c = xr_n; xu_c = xu_n;
    }

    asm volatile("barrier.cluster.arrive.aligned;" ::: "memory");
    asm volatile("barrier.cluster.wait.aligned;" ::: "memory");
}

// ---------------- launch ------------------------------------------------------
extern "C" void kernel_launch(void* const* d_in, const int* in_sizes, int n_in,
                              void* d_out, int out_size) {
    const float* inp  = (const float*)d_in[0];
    const float* Wi_w = (const float*)d_in[1];
    const float* Wi_b = (const float*)d_in[2];
    const float* Wx_w = (const float*)d_in[3];
    const float* Wx_b = (const float*)d_in[4];
    const float* Ux_w = (const float*)d_in[5];
    const float* Ux_b = (const float*)d_in[6];
    const float* Rx_w = (const float*)d_in[7];
    const float* Rx_b = (const float*)d_in[8];
    const float* Wr_w = (const float*)d_in[9];
    const float* Wr_b = (const float*)d_in[10];
    const float* Wu_w = (const float*)d_in[11];
    const float* Wu_b = (const float*)d_in[12];
    const float* Wo_w = (const float*)d_in[13];
    const float* Wo_b = (const float*)d_in[14];

    void *pxh, *pxg, *phf, *phb, *pwi, *pwg, *pwo, *pbg;
    cudaGetSymbolAddress(&pxh, g_xh);
    cudaGetSymbolAddress(&pxg, g_xg);
    cudaGetSymbolAddress(&phf, g_hf);
    cudaGetSymbolAddress(&phb, g_hb);
    cudaGetSymbolAddress(&pwi, g_wi_h);
    cudaGetSymbolAddress(&pwg, g_wg_h);
    cudaGetSymbolAddress(&pwo, g_wo_h);
    cudaGetSymbolAddress(&pbg, g_bg);

    cudaFuncSetAttribute(gemm_tc<0, 1>, cudaFuncAttributeMaxDynamicSharedMemorySize, SMEM_GEMM_BYTES);
    cudaFuncSetAttribute(gemm_tc<1, 0>, cudaFuncAttributeMaxDynamicSharedMemorySize, SMEM_GEMM_BYTES);
    cudaFuncSetAttribute(gemm_tc<2, 0>, cudaFuncAttributeMaxDynamicSharedMemorySize, SMEM_GEMM_BYTES);
    cudaFuncSetAttribute(gru_rec_tc, cudaFuncAttributeMaxDynamicSharedMemorySize, GRU_SMEM);

    // pack weights
    prep_kernel<<<768, 256>>>(Wi_w, Wx_w, Wx_b, Ux_w, Ux_b, Rx_w, Rx_b,
                              Wr_w, Wr_b, Wu_w, Wu_b, Wo_w);

    // x = fp16(inputs @ Wi + bi)          [65536,256] x [256,256]
    gemm_tc<0, 1><<<dim3(2, 512), 256, SMEM_GEMM_BYTES>>>(
        inp, nullptr, (const __half*)pwi, Wi_b, pxh, 256);

    // xg = x @ [Wx|Ux|Rx] + biases        [65536,256] x [256,768] -> fp32
    gemm_tc<1, 0><<<dim3(6, 512), 256, SMEM_GEMM_BYTES>>>(
        pxh, nullptr, (const __half*)pwg, (const float*)pbg, pxg, 768);

    // bidirectional recurrence: 8 clusters of 4 CTAs, tensor-core steps
    gru_rec_tc<<<32, 512, GRU_SMEM>>>();

    // out = (hf + hb) @ Wo + bo           [65536,256] x [256,256] -> fp32
    gemm_tc<2, 0><<<dim3(2, 512), 256, SMEM_GEMM_BYTES>>>(
        phf, phb, (const __half*)pwo, Wo_b, d_out, 256);
}